// round 2
// baseline (speedup 1.0000x reference)
#include <cuda_runtime.h>
#include <math.h>

// ---- problem constants ----
#define BSZ   32
#define TT    22
#define PP    196
#define DE    2048
#define EE    512
#define HH    512
#define AA    512
#define VV    30000
#define TDEC  20
#define XX    2560   // E + DE
#define G4    2048   // 4*H

// ---- output layout (float32, concatenated in reference return order) ----
#define OFF_PRED  0
#define OFF_ALPHA (BSZ*TDEC*VV)                 // 19,200,000
#define OFF_CAPS  (OFF_ALPHA + BSZ*TDEC*PP)    // 19,325,440
#define OFF_LEN   (OFF_CAPS + BSZ*TT)          // 19,326,144
#define OFF_SORT  (OFF_LEN + BSZ)              // 19,326,176

// ---- device scratch (static globals; no allocation allowed) ----
__device__ float g_att1[BSZ*PP*AA];      // 12.8 MB
__device__ float g_h[BSZ*HH];
__device__ float g_c[BSZ*HH];
__device__ float g_att2[BSZ*AA];
__device__ float g_gateraw[BSZ*DE];
__device__ float g_alpha[BSZ*PP];
__device__ float g_xbuf[BSZ*XX];
__device__ float g_gates[BSZ*G4];
__device__ float g_Hall[TDEC*BSZ*HH];
__device__ float g_mean[BSZ*DE];
__device__ int   g_sortind[BSZ];
__device__ int   g_declen[BSZ];
__device__ int   g_caps[BSZ*TT];
__device__ int   g_rowmapA[BSZ*PP];
__device__ int   g_rowmapC[BSZ*TDEC];
__device__ int   g_activeC[BSZ*TDEC];

__device__ __forceinline__ float sigm(float x) { return 1.0f / (1.0f + expf(-x)); }

// ============================================================
// Setup: stable descending argsort of lengths, caps gather,
// row maps + masks for the big GEMMs, small outputs.
// ============================================================
__global__ void k_setup(const int* __restrict__ captions,
                        const int* __restrict__ cap_len,
                        float* __restrict__ out_caps,
                        float* __restrict__ out_len,
                        float* __restrict__ out_sort) {
    int tid = threadIdx.x;
    __shared__ int s_len[BSZ];
    __shared__ int s_sort[BSZ];
    __shared__ int s_dec[BSZ];
    if (tid < BSZ) s_len[tid] = cap_len[tid];
    __syncthreads();
    if (tid < BSZ) {
        int li = s_len[tid];
        int rank = 0;
        for (int j = 0; j < BSZ; j++) {
            int lj = s_len[j];
            if (lj > li || (lj == li && j < tid)) rank++;
        }
        s_sort[rank] = tid;   // stable descending
    }
    __syncthreads();
    if (tid < BSZ) {
        int src = s_sort[tid];
        g_sortind[tid] = src;
        int L = s_len[src];
        g_declen[tid] = L - 1;
        s_dec[tid]    = L - 1;
        out_len[tid]  = (float)L;
        out_sort[tid] = (float)src;
    }
    __syncthreads();
    for (int i = tid; i < BSZ*TT; i += blockDim.x) {
        int b = i / TT, t = i % TT;
        int v = captions[t*BSZ + s_sort[b]];
        g_caps[i] = v;
        out_caps[i] = (float)v;
    }
    for (int i = tid; i < BSZ*PP; i += blockDim.x) {
        int b = i / PP, p = i % PP;
        g_rowmapA[i] = s_sort[b]*PP + p;
    }
    for (int i = tid; i < BSZ*TDEC; i += blockDim.x) {
        int b = i / TDEC, t = i % TDEC;
        g_rowmapC[i] = t*BSZ + b;              // Hall is [t][b][h]
        g_activeC[i] = (t < s_dec[b]) ? 1 : 0;
    }
}

// ============================================================
// mean_enc[b][d] = mean_p features[sort_ind[b]][p][d]
// ============================================================
__global__ void k_mean(const float* __restrict__ feat) {
    int b = blockIdx.y;
    int d = blockIdx.x*256 + threadIdx.x;
    const float* base = feat + (size_t)g_sortind[b]*PP*DE + d;
    float s = 0.f;
    #pragma unroll 4
    for (int p = 0; p < PP; p++) s += base[(size_t)p*DE];
    g_mean[b*DE + d] = s * (1.0f/PP);
}

// ============================================================
// h0/c0: [32,2048] @ [2048,512] x2, warp-tiled (4 cols x 8 b)
// virtual cols: [0,512) -> h0 (Wh0), [512,1024) -> c0 (Wc0)
// ============================================================
__global__ void __launch_bounds__(256) k_h0c0(const float* __restrict__ Wh0, const float* __restrict__ bh0,
                                              const float* __restrict__ Wc0, const float* __restrict__ bc0) {
    __shared__ float xs[BSZ][128];
    int tid = threadIdx.x, lane = tid & 31, w = tid >> 5;
    int c0 = blockIdx.x*8 + (w & 1)*4;
    int b0 = (w >> 1)*8;
    float acc[4][8];
    #pragma unroll
    for (int i = 0; i < 4; i++)
        #pragma unroll
        for (int jx = 0; jx < 8; jx++) acc[i][jx] = 0.f;

    for (int kt = 0; kt < DE/128; kt++) {
        #pragma unroll
        for (int s = 0; s < 16; s++) {
            int idx = tid + s*256;
            int bb = idx >> 7, kk = idx & 127;
            xs[bb][kk] = g_mean[bb*DE + kt*128 + kk];
        }
        __syncthreads();
        #pragma unroll
        for (int kk4 = 0; kk4 < 4; kk4++) {
            int k = kt*128 + kk4*32 + lane;
            float wv[4];
            #pragma unroll
            for (int cc = 0; cc < 4; cc++) {
                int col = c0 + cc;
                wv[cc] = (col < HH) ? Wh0[(size_t)k*HH + col] : Wc0[(size_t)k*HH + col - HH];
            }
            #pragma unroll
            for (int cc = 0; cc < 4; cc++)
                #pragma unroll
                for (int bb = 0; bb < 8; bb++)
                    acc[cc][bb] = fmaf(wv[cc], xs[b0+bb][kk4*32+lane], acc[cc][bb]);
        }
        __syncthreads();
    }
    float out = 0.f;
    #pragma unroll
    for (int cc = 0; cc < 4; cc++)
        #pragma unroll
        for (int bb = 0; bb < 8; bb++) {
            float v = acc[cc][bb];
            #pragma unroll
            for (int off = 16; off; off >>= 1) v += __shfl_xor_sync(0xffffffffu, v, off);
            if (lane == cc*8 + bb) out = v;
        }
    int cc = lane >> 3, bb = lane & 7;
    int col = c0 + cc, b = b0 + bb;
    if (col < HH) g_h[b*HH + col]      = out + bh0[col];
    else          g_c[b*HH + col - HH] = out + bc0[col - HH];
}

// ============================================================
// Step S1: att2 = h@Wda + bda ; gate_raw = h@Wfb + bfb
// virtual cols: [0,512) att2, [512,2560) gate_raw. K=512.
// ============================================================
__global__ void __launch_bounds__(256) k_s1(const float* __restrict__ Wda, const float* __restrict__ bda,
                                            const float* __restrict__ Wfb, const float* __restrict__ bfb) {
    __shared__ float xs[BSZ][128];
    int tid = threadIdx.x, lane = tid & 31, w = tid >> 5;
    int c0 = blockIdx.x*8 + (w & 1)*4;
    int b0 = (w >> 1)*8;
    float acc[4][8];
    #pragma unroll
    for (int i = 0; i < 4; i++)
        #pragma unroll
        for (int jx = 0; jx < 8; jx++) acc[i][jx] = 0.f;

    for (int kt = 0; kt < HH/128; kt++) {
        #pragma unroll
        for (int s = 0; s < 16; s++) {
            int idx = tid + s*256;
            int bb = idx >> 7, kk = idx & 127;
            xs[bb][kk] = g_h[bb*HH + kt*128 + kk];
        }
        __syncthreads();
        #pragma unroll
        for (int kk4 = 0; kk4 < 4; kk4++) {
            int k = kt*128 + kk4*32 + lane;
            float wv[4];
            #pragma unroll
            for (int cc = 0; cc < 4; cc++) {
                int col = c0 + cc;
                wv[cc] = (col < AA) ? Wda[(size_t)k*AA + col] : Wfb[(size_t)k*DE + col - AA];
            }
            #pragma unroll
            for (int cc = 0; cc < 4; cc++)
                #pragma unroll
                for (int bb = 0; bb < 8; bb++)
                    acc[cc][bb] = fmaf(wv[cc], xs[b0+bb][kk4*32+lane], acc[cc][bb]);
        }
        __syncthreads();
    }
    float out = 0.f;
    #pragma unroll
    for (int cc = 0; cc < 4; cc++)
        #pragma unroll
        for (int bb = 0; bb < 8; bb++) {
            float v = acc[cc][bb];
            #pragma unroll
            for (int off = 16; off; off >>= 1) v += __shfl_xor_sync(0xffffffffu, v, off);
            if (lane == cc*8 + bb) out = v;
        }
    int cc = lane >> 3, bb = lane & 7;
    int col = c0 + cc, b = b0 + bb;
    if (col < AA) g_att2[b*AA + col]         = out + bda[col];
    else          g_gateraw[b*DE + col - AA] = out + bfb[col - AA];
}

// ============================================================
// Step S2: e = relu(att1 + att2)@Wfa + bfa ; softmax -> alpha
// Also gathers this step's embedding into xbuf[:,0:512] and
// writes masked alphas to the output.
// One block per b (256 threads).
// ============================================================
__global__ void __launch_bounds__(256) k_s2(int t, const float* __restrict__ emb,
                                            const float* __restrict__ Wfa, const float* __restrict__ bfa,
                                            float* __restrict__ out_alphas) {
    int b = blockIdx.x, tid = threadIdx.x, lane = tid & 31, w = tid >> 5;
    __shared__ float att2s[AA], wfas[AA], es[PP], sred[256];

    att2s[tid]       = g_att2[b*AA + tid];
    att2s[tid + 256] = g_att2[b*AA + tid + 256];
    wfas[tid]        = Wfa[tid];
    wfas[tid + 256]  = Wfa[tid + 256];
    {   // embedding gather for this step
        int tok = g_caps[b*TT + t];
        g_xbuf[b*XX + tid]       = emb[(size_t)tok*EE + tid];
        g_xbuf[b*XX + tid + 256] = emb[(size_t)tok*EE + tid + 256];
    }
    __syncthreads();

    float bfa0 = bfa[0];
    for (int p = w; p < PP; p += 8) {
        const float* row = g_att1 + ((size_t)b*PP + p)*AA;
        float acc = 0.f;
        #pragma unroll 4
        for (int a = lane; a < AA; a += 32) {
            float v = row[a] + att2s[a];
            v = fmaxf(v, 0.f);
            acc = fmaf(v, wfas[a], acc);
        }
        #pragma unroll
        for (int off = 16; off; off >>= 1) acc += __shfl_xor_sync(0xffffffffu, acc, off);
        if (lane == 0) es[p] = acc + bfa0;
    }
    __syncthreads();

    // softmax over 196
    sred[tid] = (tid < PP) ? es[tid] : -3.0e38f;
    __syncthreads();
    for (int s = 128; s > 0; s >>= 1) { if (tid < s) sred[tid] = fmaxf(sred[tid], sred[tid+s]); __syncthreads(); }
    float mx = sred[0];
    __syncthreads();
    float ex = (tid < PP) ? expf(es[tid] - mx) : 0.f;
    sred[tid] = ex;
    __syncthreads();
    for (int s = 128; s > 0; s >>= 1) { if (tid < s) sred[tid] += sred[tid+s]; __syncthreads(); }
    float inv = 1.0f / sred[0];
    if (tid < PP) {
        float al = ex * inv;
        g_alpha[b*PP + tid] = al;
        int active = (t < g_declen[b]);
        out_alphas[((size_t)b*TDEC + t)*PP + tid] = active ? al : 0.f;
    }
}

// ============================================================
// Step S3: awe[b][d] = sum_p alpha[b][p]*enc[b][p][d];
// xbuf[b][512+d] = sigmoid(gate_raw[b][d]) * awe
// ============================================================
__global__ void __launch_bounds__(256) k_s3(const float* __restrict__ feat) {
    int b = blockIdx.y;
    int d = blockIdx.x*256 + threadIdx.x;
    __shared__ float als[PP];
    if (threadIdx.x < PP) als[threadIdx.x] = g_alpha[b*PP + threadIdx.x];
    __syncthreads();
    const float* base = feat + (size_t)g_sortind[b]*PP*DE + d;
    float s = 0.f;
    #pragma unroll 4
    for (int p = 0; p < PP; p++) s = fmaf(als[p], base[(size_t)p*DE], s);
    float gr = g_gateraw[b*DE + d];
    g_xbuf[b*XX + EE + d] = sigm(gr) * s;
}

// ============================================================
// Step S4: gates = x@Wih^T + bih + h@Whh^T + bhh  (virtual K=3072)
// block = 16 j x 16 b; warp = 4 j x 8 b. grid (128, 2).
// ============================================================
__global__ void __launch_bounds__(256) k_s4(const float* __restrict__ Wih, const float* __restrict__ bih,
                                            const float* __restrict__ Whh, const float* __restrict__ bhh) {
    __shared__ float xs[16][128];
    int tid = threadIdx.x, lane = tid & 31, w = tid >> 5;
    int jBlock = blockIdx.x*16, bBlock = blockIdx.y*16;
    int j0 = jBlock + (w >> 1)*4;
    int bq = (w & 1);
    int b0loc = bq*8;
    float acc[4][8];
    #pragma unroll
    for (int i = 0; i < 4; i++)
        #pragma unroll
        for (int jx = 0; jx < 8; jx++) acc[i][jx] = 0.f;

    for (int kt = 0; kt < 24; kt++) {   // 24*128 = 3072 = 2560 + 512
        #pragma unroll
        for (int s = 0; s < 8; s++) {
            int idx = tid + s*256;
            int bb = idx >> 7, kk = idx & 127;
            int gk = kt*128 + kk;
            int b = bBlock + bb;
            xs[bb][kk] = (gk < XX) ? g_xbuf[b*XX + gk] : g_h[b*HH + gk - XX];
        }
        __syncthreads();
        #pragma unroll
        for (int kk4 = 0; kk4 < 4; kk4++) {
            int gk = kt*128 + kk4*32 + lane;
            float wv[4];
            #pragma unroll
            for (int cc = 0; cc < 4; cc++) {
                int j = j0 + cc;
                wv[cc] = (gk < XX) ? Wih[(size_t)j*XX + gk] : Whh[(size_t)j*HH + gk - XX];
            }
            #pragma unroll
            for (int cc = 0; cc < 4; cc++)
                #pragma unroll
                for (int bb = 0; bb < 8; bb++)
                    acc[cc][bb] = fmaf(wv[cc], xs[b0loc+bb][kk4*32+lane], acc[cc][bb]);
        }
        __syncthreads();
    }
    float out = 0.f;
    #pragma unroll
    for (int cc = 0; cc < 4; cc++)
        #pragma unroll
        for (int bb = 0; bb < 8; bb++) {
            float v = acc[cc][bb];
            #pragma unroll
            for (int off = 16; off; off >>= 1) v += __shfl_xor_sync(0xffffffffu, v, off);
            if (lane == cc*8 + bb) out = v;
        }
    int cc = lane >> 3, bb = lane & 7;
    int j = j0 + cc;
    int b = bBlock + b0loc + bb;
    g_gates[b*G4 + j] = out + bih[j] + bhh[j];
}

// ============================================================
// Step S5: LSTM elementwise + masked state update + Hall store
// ============================================================
__global__ void k_s5(int t) {
    int b = blockIdx.x, j = threadIdx.x;
    float gi = g_gates[b*G4 + j];
    float gf = g_gates[b*G4 + 512 + j];
    float gg = g_gates[b*G4 + 1024 + j];
    float go = g_gates[b*G4 + 1536 + j];
    float c  = g_c[b*HH + j];
    float cn = sigm(gf)*c + sigm(gi)*tanhf(gg);
    float hn = sigm(go)*tanhf(cn);
    if (t < g_declen[b]) { g_h[b*HH + j] = hn; g_c[b*HH + j] = cn; }
    g_Hall[((size_t)t*BSZ + b)*HH + j] = hn;
}

// ============================================================
// Big SGEMM: C = rowmask ? (A[rowmap] @ B + bias) : 0
// 128x128x8 tile, 256 thr, 8x8 microtile, float4 loads.
// mode: 0 = plain, 1 = att1 (A-gather, C=g_att1), 2 = preds
//       (A=g_Hall via rowmap, row-mask, C=out)
// ============================================================
__global__ void __launch_bounds__(256) k_gemm(const float* __restrict__ Aptr, int lda,
                                              const float* __restrict__ Bptr, int ldb,
                                              const float* __restrict__ bias,
                                              float* __restrict__ Cptr, int ldc,
                                              int M, int N, int K, int mode) {
    __shared__ float As[8][128];
    __shared__ float Bs[8][128];
    const int* rowmap    = (mode == 1) ? g_rowmapA : (mode == 2) ? g_rowmapC : nullptr;
    const int* rowactive = (mode == 2) ? g_activeC : nullptr;
    const float* Ause = (mode == 2) ? g_Hall : Aptr;
    float* Cuse = (mode == 1) ? g_att1 : Cptr;

    int tid = threadIdx.x;
    int rowBase = blockIdx.y*128, colBase = blockIdx.x*128;
    int tx = tid & 15, ty = tid >> 4;
    float acc[8][8];
    #pragma unroll
    for (int i = 0; i < 8; i++)
        #pragma unroll
        for (int jx = 0; jx < 8; jx++) acc[i][jx] = 0.f;

    int arow = tid >> 1;        int acol = (tid & 1)*4;
    int brow = tid >> 5;        int bcol = (tid & 31)*4;
    int gRow = rowBase + arow;
    bool aval = gRow < M;
    int amap = aval ? (rowmap ? rowmap[gRow] : gRow) : 0;
    int gCol = colBase + bcol;
    bool bval = gCol < N;       // N % 4 == 0, float4-safe

    for (int k0 = 0; k0 < K; k0 += 8) {
        float4 av = aval ? *(const float4*)(Ause + (size_t)amap*lda + k0 + acol)
                         : make_float4(0.f,0.f,0.f,0.f);
        float4 bv = bval ? *(const float4*)(Bptr + (size_t)(k0 + brow)*ldb + gCol)
                         : make_float4(0.f,0.f,0.f,0.f);
        As[acol+0][arow] = av.x; As[acol+1][arow] = av.y;
        As[acol+2][arow] = av.z; As[acol+3][arow] = av.w;
        *(float4*)&Bs[brow][bcol] = bv;
        __syncthreads();
        #pragma unroll
        for (int k = 0; k < 8; k++) {
            float ra[8], rb[8];
            #pragma unroll
            for (int i = 0; i < 8; i++) ra[i] = As[k][ty*8 + i];
            #pragma unroll
            for (int i = 0; i < 8; i++) rb[i] = Bs[k][tx*8 + i];
            #pragma unroll
            for (int i = 0; i < 8; i++)
                #pragma unroll
                for (int jx = 0; jx < 8; jx++)
                    acc[i][jx] = fmaf(ra[i], rb[jx], acc[i][jx]);
        }
        __syncthreads();
    }

    #pragma unroll
    for (int i = 0; i < 8; i++) {
        int r = rowBase + ty*8 + i;
        if (r >= M) continue;
        int act = rowactive ? rowactive[r] : 1;
        #pragma unroll
        for (int jx = 0; jx < 8; jx++) {
            int cI = colBase + tx*8 + jx;
            if (cI < N)
                Cuse[(size_t)r*ldc + cI] = act ? (acc[i][jx] + (bias ? bias[cI] : 0.f)) : 0.f;
        }
    }
}

// ============================================================
extern "C" void kernel_launch(void* const* d_in, const int* in_sizes, int n_in,
                              void* d_out, int out_size) {
    const float* feat     = (const float*)d_in[0];
    const int*   captions = (const int*)  d_in[1];
    const int*   caplen   = (const int*)  d_in[2];
    const float* emb      = (const float*)d_in[3];
    const float* Wea = (const float*)d_in[4];  const float* bea = (const float*)d_in[5];
    const float* Wda = (const float*)d_in[6];  const float* bda = (const float*)d_in[7];
    const float* Wfa = (const float*)d_in[8];  const float* bfa = (const float*)d_in[9];
    const float* Wih = (const float*)d_in[10]; const float* bih = (const float*)d_in[11];
    const float* Whh = (const float*)d_in[12]; const float* bhh = (const float*)d_in[13];
    const float* Wh0 = (const float*)d_in[14]; const float* bh0 = (const float*)d_in[15];
    const float* Wc0 = (const float*)d_in[16]; const float* bc0 = (const float*)d_in[17];
    const float* Wfb = (const float*)d_in[18]; const float* bfb = (const float*)d_in[19];
    const float* Wout = (const float*)d_in[20]; const float* bout = (const float*)d_in[21];

    float* out = (float*)d_out;
    float* out_pred  = out + OFF_PRED;
    float* out_alpha = out + OFF_ALPHA;
    float* out_caps  = out + OFF_CAPS;
    float* out_len   = out + OFF_LEN;
    float* out_sort  = out + OFF_SORT;

    // ---- prologue ----
    k_setup<<<1, 256>>>(captions, caplen, out_caps, out_len, out_sort);
    k_mean<<<dim3(DE/256, BSZ), 256>>>(feat);
    k_h0c0<<<128, 256>>>(Wh0, bh0, Wc0, bc0);
    // att1 = enc @ Wea + bea : M=6272, N=512, K=2048 (A gathered via rowmapA)
    k_gemm<<<dim3(512/128, 6272/128), 256>>>(feat, DE, Wea, AA, bea,
                                             nullptr, AA, BSZ*PP, AA, DE, 1);

    // ---- recurrence (20 steps) ----
    for (int t = 0; t < TDEC; t++) {
        k_s1<<<XX/8, 256>>>(Wda, bda, Wfb, bfb);
        k_s2<<<BSZ, 256>>>(t, emb, Wfa, bfa, out_alpha);
        k_s3<<<dim3(DE/256, BSZ), 256>>>(feat);
        k_s4<<<dim3(G4/16, BSZ/16), 256>>>(Wih, bih, Whh, bhh);
        k_s5<<<BSZ, 512>>>(t);
    }

    // ---- epilogue: preds = Hall @ Wout + bout (masked rows -> 0) ----
    // M=640, N=30000, K=512
    k_gemm<<<dim3((VV + 127)/128, (BSZ*TDEC)/128), 256>>>(nullptr, HH, Wout, VV, bout,
                                                          out_pred, VV, BSZ*TDEC, VV, HH, 2);
}

// round 3
// speedup vs baseline: 1.6194x; 1.6194x over previous
#include <cuda_runtime.h>
#include <math.h>

// ---- problem constants ----
#define BSZ   32
#define TT    22
#define PP    196
#define DE    2048
#define EE    512
#define HH    512
#define AA    512
#define VV    30000
#define TDEC  20
#define XX    2560   // E + DE
#define G4    2048   // 4*H
#define KAW   2048   // awe part of K in LSTM gemm
#define KS4   2560   // awe + h

// ---- output layout ----
#define OFF_PRED  0
#define OFF_ALPHA (BSZ*TDEC*VV)
#define OFF_CAPS  (OFF_ALPHA + BSZ*TDEC*PP)
#define OFF_LEN   (OFF_CAPS + BSZ*TT)
#define OFF_SORT  (OFF_LEN + BSZ)

// ---- device scratch ----
__device__ float g_att1[BSZ*PP*AA];        // 12.8 MB
__device__ float g_hbuf[2*BSZ*HH];
__device__ float g_c[BSZ*HH];
__device__ float g_att2[BSZ*AA];
__device__ float g_gateraw[BSZ*DE];
__device__ float g_alpha[BSZ*PP];
__device__ float g_escore[BSZ*PP];
__device__ float g_xawe[BSZ*KAW];
__device__ float g_Hall[TDEC*BSZ*HH];
__device__ float g_mean[BSZ*DE];
__device__ float g_embX[TDEC*BSZ*EE];
__device__ float g_WihET[EE*G4];           // 4 MB transposed emb-part of Wih
__device__ float g_pre[TDEC*BSZ*G4];       // 5 MB precomputed emb contribution
__device__ int   g_sortind[BSZ];
__device__ int   g_declen[BSZ];
__device__ int   g_caps[BSZ*TT];
__device__ int   g_rowmapA[BSZ*PP];
__device__ int   g_rowmapC[BSZ*TDEC];
__device__ int   g_activeC[BSZ*TDEC];

__device__ __forceinline__ float sigm(float x) { return 1.0f / (1.0f + expf(-x)); }

// ============================================================
// Setup
// ============================================================
__global__ void k_setup(const int* __restrict__ captions,
                        const int* __restrict__ cap_len,
                        float* __restrict__ out_caps,
                        float* __restrict__ out_len,
                        float* __restrict__ out_sort) {
    int tid = threadIdx.x;
    __shared__ int s_len[BSZ];
    __shared__ int s_sort[BSZ];
    __shared__ int s_dec[BSZ];
    if (tid < BSZ) s_len[tid] = cap_len[tid];
    __syncthreads();
    if (tid < BSZ) {
        int li = s_len[tid];
        int rank = 0;
        for (int j = 0; j < BSZ; j++) {
            int lj = s_len[j];
            if (lj > li || (lj == li && j < tid)) rank++;
        }
        s_sort[rank] = tid;
    }
    __syncthreads();
    if (tid < BSZ) {
        int src = s_sort[tid];
        g_sortind[tid] = src;
        int L = s_len[src];
        g_declen[tid] = L - 1;
        s_dec[tid]    = L - 1;
        out_len[tid]  = (float)L;
        out_sort[tid] = (float)src;
    }
    __syncthreads();
    for (int i = tid; i < BSZ*TT; i += blockDim.x) {
        int b = i / TT, t = i % TT;
        int v = captions[t*BSZ + s_sort[b]];
        g_caps[i] = v;
        out_caps[i] = (float)v;
    }
    for (int i = tid; i < BSZ*PP; i += blockDim.x) {
        int b = i / PP, p = i % PP;
        g_rowmapA[i] = s_sort[b]*PP + p;
    }
    for (int i = tid; i < BSZ*TDEC; i += blockDim.x) {
        int b = i / TDEC, t = i % TDEC;
        g_rowmapC[i] = t*BSZ + b;
        g_activeC[i] = (t < s_dec[b]) ? 1 : 0;
    }
}

// ============================================================
// Gather embeddings for all decode steps: g_embX[t*B+b][:]
// ============================================================
__global__ void k_embgather(const float* __restrict__ emb) {
    int t = blockIdx.x, b = blockIdx.y;
    int tok = g_caps[b*TT + t];
    const float* src = emb + (size_t)tok*EE;
    float* dst = g_embX + ((size_t)t*BSZ + b)*EE;
    for (int e = threadIdx.x; e < EE; e += blockDim.x) dst[e] = src[e];
}

// ============================================================
// Transpose emb-part of Wih: g_WihET[k][j] = Wih[j][k], k<512
// ============================================================
__global__ void k_transWihE(const float* __restrict__ Wih) {
    __shared__ float ts[32][33];
    int j0 = blockIdx.x*32, k0 = blockIdx.y*32;
    int tx = threadIdx.x & 31, tyy = threadIdx.x >> 5;
    for (int r = tyy; r < 32; r += 8)
        ts[r][tx] = Wih[(size_t)(j0 + r)*XX + k0 + tx];
    __syncthreads();
    for (int r = tyy; r < 32; r += 8)
        g_WihET[(size_t)(k0 + r)*G4 + j0 + tx] = ts[tx][r];
}

// ============================================================
// mean_enc
// ============================================================
__global__ void k_mean(const float* __restrict__ feat) {
    int b = blockIdx.y;
    int d = blockIdx.x*256 + threadIdx.x;
    const float* base = feat + (size_t)g_sortind[b]*PP*DE + d;
    float s = 0.f;
    #pragma unroll 4
    for (int p = 0; p < PP; p++) s += base[(size_t)p*DE];
    g_mean[b*DE + d] = s * (1.0f/PP);
}

// ============================================================
// h0/c0
// ============================================================
__global__ void __launch_bounds__(256) k_h0c0(const float* __restrict__ Wh0, const float* __restrict__ bh0,
                                              const float* __restrict__ Wc0, const float* __restrict__ bc0) {
    __shared__ float xs[BSZ][128];
    int tid = threadIdx.x, lane = tid & 31, w = tid >> 5;
    int c0 = blockIdx.x*8 + (w & 1)*4;
    int b0 = (w >> 1)*8;
    float acc[4][8];
    #pragma unroll
    for (int i = 0; i < 4; i++)
        #pragma unroll
        for (int jx = 0; jx < 8; jx++) acc[i][jx] = 0.f;

    for (int kt = 0; kt < DE/128; kt++) {
        #pragma unroll
        for (int s = 0; s < 16; s++) {
            int idx = tid + s*256;
            int bb = idx >> 7, kk = idx & 127;
            xs[bb][kk] = g_mean[bb*DE + kt*128 + kk];
        }
        __syncthreads();
        #pragma unroll
        for (int kk4 = 0; kk4 < 4; kk4++) {
            int k = kt*128 + kk4*32 + lane;
            float wv[4];
            #pragma unroll
            for (int cc = 0; cc < 4; cc++) {
                int col = c0 + cc;
                wv[cc] = (col < HH) ? Wh0[(size_t)k*HH + col] : Wc0[(size_t)k*HH + col - HH];
            }
            #pragma unroll
            for (int cc = 0; cc < 4; cc++)
                #pragma unroll
                for (int bb = 0; bb < 8; bb++)
                    acc[cc][bb] = fmaf(wv[cc], xs[b0+bb][kk4*32+lane], acc[cc][bb]);
        }
        __syncthreads();
    }
    float out = 0.f;
    #pragma unroll
    for (int cc = 0; cc < 4; cc++)
        #pragma unroll
        for (int bb = 0; bb < 8; bb++) {
            float v = acc[cc][bb];
            #pragma unroll
            for (int off = 16; off; off >>= 1) v += __shfl_xor_sync(0xffffffffu, v, off);
            if (lane == cc*8 + bb) out = v;
        }
    int cc = lane >> 3, bb = lane & 7;
    int col = c0 + cc, b = b0 + bb;
    if (col < HH) g_hbuf[b*HH + col]     = out + bh0[col];
    else          g_c[b*HH + col - HH]   = out + bc0[col - HH];
}

// ============================================================
// S1: att2 = h@Wda + bda ; gate_raw = h@Wfb + bfb
// ============================================================
__global__ void __launch_bounds__(256) k_s1(const float* __restrict__ hcur,
                                            const float* __restrict__ Wda, const float* __restrict__ bda,
                                            const float* __restrict__ Wfb, const float* __restrict__ bfb) {
    __shared__ float xs[BSZ][128];
    int tid = threadIdx.x, lane = tid & 31, w = tid >> 5;
    int c0 = blockIdx.x*8 + (w & 1)*4;
    int b0 = (w >> 1)*8;
    float acc[4][8];
    #pragma unroll
    for (int i = 0; i < 4; i++)
        #pragma unroll
        for (int jx = 0; jx < 8; jx++) acc[i][jx] = 0.f;

    for (int kt = 0; kt < HH/128; kt++) {
        #pragma unroll
        for (int s = 0; s < 16; s++) {
            int idx = tid + s*256;
            int bb = idx >> 7, kk = idx & 127;
            xs[bb][kk] = hcur[bb*HH + kt*128 + kk];
        }
        __syncthreads();
        #pragma unroll
        for (int kk4 = 0; kk4 < 4; kk4++) {
            int k = kt*128 + kk4*32 + lane;
            float wv[4];
            #pragma unroll
            for (int cc = 0; cc < 4; cc++) {
                int col = c0 + cc;
                wv[cc] = (col < AA) ? Wda[(size_t)k*AA + col] : Wfb[(size_t)k*DE + col - AA];
            }
            #pragma unroll
            for (int cc = 0; cc < 4; cc++)
                #pragma unroll
                for (int bb = 0; bb < 8; bb++)
                    acc[cc][bb] = fmaf(wv[cc], xs[b0+bb][kk4*32+lane], acc[cc][bb]);
        }
        __syncthreads();
    }
    float out = 0.f;
    #pragma unroll
    for (int cc = 0; cc < 4; cc++)
        #pragma unroll
        for (int bb = 0; bb < 8; bb++) {
            float v = acc[cc][bb];
            #pragma unroll
            for (int off = 16; off; off >>= 1) v += __shfl_xor_sync(0xffffffffu, v, off);
            if (lane == cc*8 + bb) out = v;
        }
    int cc = lane >> 3, bb = lane & 7;
    int col = c0 + cc, b = b0 + bb;
    if (col < AA) g_att2[b*AA + col]         = out + bda[col];
    else          g_gateraw[b*DE + col - AA] = out + bfb[col - AA];
}

// ============================================================
// S2a: scores e[b,p] = relu(att1+att2)@Wfa + bfa  (1 warp/row)
// grid (25, 32) x 256
// ============================================================
__global__ void __launch_bounds__(256) k_s2a(const float* __restrict__ Wfa, const float* __restrict__ bfa) {
    int b = blockIdx.y;
    int tid = threadIdx.x, lane = tid & 31, w = tid >> 5;
    __shared__ float att2s[AA], wfas[AA];
    for (int i = tid; i < AA; i += 256) {
        att2s[i] = g_att2[b*AA + i];
        wfas[i]  = Wfa[i];
    }
    __syncthreads();
    int p = blockIdx.x*8 + w;
    if (p >= PP) return;
    const float* row = g_att1 + ((size_t)b*PP + p)*AA;
    float acc = 0.f;
    #pragma unroll
    for (int a0 = 0; a0 < AA; a0 += 128) {
        #pragma unroll
        for (int q = 0; q < 4; q++) {
            int a = a0 + q*32 + lane;
            float v = fmaxf(row[a] + att2s[a], 0.f);
            acc = fmaf(v, wfas[a], acc);
        }
    }
    #pragma unroll
    for (int off = 16; off; off >>= 1) acc += __shfl_xor_sync(0xffffffffu, acc, off);
    if (lane == 0) g_escore[b*PP + p] = acc + bfa[0];
}

// ============================================================
// S2b: softmax over P + masked alpha output
// ============================================================
__global__ void __launch_bounds__(256) k_s2b(int t, float* __restrict__ out_alphas) {
    int b = blockIdx.x, tid = threadIdx.x;
    __shared__ float sred[256];
    float e = (tid < PP) ? g_escore[b*PP + tid] : -3.0e38f;
    sred[tid] = e;
    __syncthreads();
    for (int s = 128; s > 0; s >>= 1) { if (tid < s) sred[tid] = fmaxf(sred[tid], sred[tid+s]); __syncthreads(); }
    float mx = sred[0];
    __syncthreads();
    float ex = (tid < PP) ? expf(e - mx) : 0.f;
    sred[tid] = ex;
    __syncthreads();
    for (int s = 128; s > 0; s >>= 1) { if (tid < s) sred[tid] += sred[tid+s]; __syncthreads(); }
    float inv = 1.0f / sred[0];
    if (tid < PP) {
        float al = ex * inv;
        g_alpha[b*PP + tid] = al;
        int active = (t < g_declen[b]);
        out_alphas[((size_t)b*TDEC + t)*PP + tid] = active ? al : 0.f;
    }
}

// ============================================================
// S3: xawe[b][d] = sigmoid(gate_raw)*sum_p alpha*enc
// ============================================================
__global__ void __launch_bounds__(256) k_s3(const float* __restrict__ feat) {
    int b = blockIdx.y;
    int d = blockIdx.x*256 + threadIdx.x;
    __shared__ float als[PP];
    if (threadIdx.x < PP) als[threadIdx.x] = g_alpha[b*PP + threadIdx.x];
    __syncthreads();
    const float* base = feat + (size_t)g_sortind[b]*PP*DE + d;
    float s = 0.f;
    #pragma unroll 7
    for (int p = 0; p < PP; p++) s = fmaf(als[p], base[(size_t)p*DE], s);
    float gr = g_gateraw[b*DE + d];
    g_xawe[b*KAW + d] = sigm(gr) * s;
}

// ============================================================
// S4 fused: gates GEMM (K=2560: awe+h) + bias + precomputed emb
//           + LSTM elementwise + masked state update + Hall.
// block: 4 hidden units x 4 gates x 32 batch. grid 128.
// h double-buffered (read cur, write 1-cur) to avoid races.
// ============================================================
__global__ void __launch_bounds__(256) k_s4f(int t, int cur,
        const float* __restrict__ Wih, const float* __restrict__ bih,
        const float* __restrict__ Whh, const float* __restrict__ bhh) {
    __shared__ float xs[BSZ][128];
    __shared__ float red[4][BSZ][33];
    __shared__ float gsum[16][BSZ];
    int tid = threadIdx.x, lane = tid & 31, w = tid >> 5;
    int jBlock = blockIdx.x*4;
    int r0 = (w >> 1)*4;
    int bh = (w & 1)*16;
    const float* hcur = g_hbuf + cur*BSZ*HH;
    float*       hnxt = g_hbuf + (1 - cur)*BSZ*HH;

    float acc[4][16];
    #pragma unroll
    for (int i = 0; i < 4; i++)
        #pragma unroll
        for (int jx = 0; jx < 16; jx++) acc[i][jx] = 0.f;

    const float* wrowIH[4];
    const float* wrowHH[4];
    #pragma unroll
    for (int cc = 0; cc < 4; cc++) {
        int v = r0 + cc;
        int wr = (v >> 2)*HH + jBlock + (v & 3);
        wrowIH[cc] = Wih + (size_t)wr*XX + EE;   // awe columns start at 512
        wrowHH[cc] = Whh + (size_t)wr*HH;
    }

    float pv[16];
    // prefetch tile 0
    #pragma unroll
    for (int s = 0; s < 16; s++) {
        int idx = tid + s*256;
        int bb = idx >> 7, kk = idx & 127;
        pv[s] = g_xawe[bb*KAW + kk];
    }
    #pragma unroll
    for (int s = 0; s < 16; s++) {
        int idx = tid + s*256;
        xs[idx >> 7][idx & 127] = pv[s];
    }
    __syncthreads();

    for (int kt = 0; kt < KS4/128; kt++) {
        if (kt + 1 < KS4/128) {
            int gk0 = (kt + 1)*128;
            #pragma unroll
            for (int s = 0; s < 16; s++) {
                int idx = tid + s*256;
                int bb = idx >> 7, kk = idx & 127;
                int gk = gk0 + kk;
                pv[s] = (gk < KAW) ? g_xawe[bb*KAW + gk] : hcur[bb*HH + gk - KAW];
            }
        }
        #pragma unroll
        for (int kk4 = 0; kk4 < 4; kk4++) {
            int gk = kt*128 + kk4*32 + lane;
            float wv[4];
            #pragma unroll
            for (int cc = 0; cc < 4; cc++)
                wv[cc] = (gk < KAW) ? wrowIH[cc][gk] : wrowHH[cc][gk - KAW];
            #pragma unroll
            for (int bb = 0; bb < 16; bb++) {
                float xv = xs[bh + bb][kk4*32 + lane];
                #pragma unroll
                for (int cc = 0; cc < 4; cc++)
                    acc[cc][bb] = fmaf(wv[cc], xv, acc[cc][bb]);
            }
        }
        __syncthreads();
        if (kt + 1 < KS4/128) {
            #pragma unroll
            for (int s = 0; s < 16; s++) {
                int idx = tid + s*256;
                xs[idx >> 7][idx & 127] = pv[s];
            }
        }
        __syncthreads();
    }

    // cross-lane reduction in 4 rounds through small smem
    for (int rnd = 0; rnd < 4; rnd++) {
        if ((w >> 1) == rnd) {
            #pragma unroll
            for (int cc = 0; cc < 4; cc++)
                #pragma unroll
                for (int bb = 0; bb < 16; bb++)
                    red[cc][bh + bb][lane] = acc[cc][bb];
        }
        __syncthreads();
        if (tid < 128) {
            int cc = tid >> 5, b = tid & 31;
            float s = 0.f;
            #pragma unroll
            for (int l = 0; l < 32; l++) s += red[cc][b][l];
            gsum[rnd*4 + cc][b] = s;
        }
        __syncthreads();
    }

    // LSTM cell
    if (tid < 128) {
        int jj = tid >> 5, b = tid & 31;
        int j = jBlock + jj;
        size_t pb = ((size_t)t*BSZ + b)*G4;
        float gi = gsum[0  + jj][b] + bih[0*HH + j] + bhh[0*HH + j] + g_pre[pb + 0*HH + j];
        float gf = gsum[4  + jj][b] + bih[1*HH + j] + bhh[1*HH + j] + g_pre[pb + 1*HH + j];
        float gg = gsum[8  + jj][b] + bih[2*HH + j] + bhh[2*HH + j] + g_pre[pb + 2*HH + j];
        float go = gsum[12 + jj][b] + bih[3*HH + j] + bhh[3*HH + j] + g_pre[pb + 3*HH + j];
        float c  = g_c[b*HH + j];
        float cn = sigm(gf)*c + sigm(gi)*tanhf(gg);
        float hn = sigm(go)*tanhf(cn);
        int active = (t < g_declen[b]);
        if (active) g_c[b*HH + j] = cn;
        hnxt[b*HH + j] = active ? hn : hcur[b*HH + j];
        g_Hall[((size_t)t*BSZ + b)*HH + j] = hn;
    }
}

// ============================================================
// Double-buffered SGEMM: 128x64 tile, K-tile 16, 128 threads,
// 8x8 microtile. mode 0: embX@WihET -> pre; mode 1: att1
// (A gather from feat, C=g_att1, bias=bea); mode 2: preds
// (A=g_Hall rowmap, row mask, bias=bout, C=out).
// ============================================================
__global__ void __launch_bounds__(128) k_gemm_db(const float* __restrict__ Aext, int lda_,
                                                 const float* __restrict__ Bext, int ldb_,
                                                 const float* __restrict__ biasext,
                                                 float* __restrict__ Cext, int ldc_,
                                                 int M, int N, int K, int mode) {
    __shared__ float As[2][16][128];
    __shared__ float Bs[2][16][64];
    int tid = threadIdx.x;
    int rowBase = blockIdx.y*128, colBase = blockIdx.x*64;

    const float* Ause; const float* Buse; const float* bias; float* Cuse;
    int lda, ldb, ldc;
    const int* rowmap = nullptr; const int* ract = nullptr;
    if (mode == 0) { Ause = g_embX; lda = EE;  Buse = g_WihET; ldb = G4; bias = nullptr; Cuse = g_pre;  ldc = G4; }
    else if (mode == 1) { Ause = Aext; lda = lda_; Buse = Bext; ldb = ldb_; bias = biasext; Cuse = g_att1; ldc = AA; rowmap = g_rowmapA; }
    else { Ause = g_Hall; lda = HH; Buse = Bext; ldb = ldb_; bias = biasext; Cuse = Cext; ldc = ldc_; rowmap = g_rowmapC; ract = g_activeC; }

    int arow = tid;                         // 0..127 (M divisible by 128)
    int gRow = rowBase + arow;
    int amap = rowmap ? rowmap[gRow] : gRow;
    const float* aptr = Ause + (size_t)amap*lda;

    int brow = tid >> 4;                    // 0..7
    int bcol = (tid & 15)*4;
    int gCol = colBase + bcol;
    bool bval = (gCol < N);

    int tx = tid & 7, ty = tid >> 3;

    float acc[8][8];
    #pragma unroll
    for (int i = 0; i < 8; i++)
        #pragma unroll
        for (int jx = 0; jx < 8; jx++) acc[i][jx] = 0.f;

    float4 aR[4], bR[2];
    // prefetch tile 0
    #pragma unroll
    for (int i = 0; i < 4; i++) aR[i] = *(const float4*)(aptr + i*4);
    #pragma unroll
    for (int i = 0; i < 2; i++)
        bR[i] = bval ? *(const float4*)(Buse + (size_t)(brow + i*8)*ldb + gCol)
                     : make_float4(0.f,0.f,0.f,0.f);
    #pragma unroll
    for (int i = 0; i < 4; i++) {
        As[0][i*4+0][arow] = aR[i].x; As[0][i*4+1][arow] = aR[i].y;
        As[0][i*4+2][arow] = aR[i].z; As[0][i*4+3][arow] = aR[i].w;
    }
    *(float4*)&Bs[0][brow][bcol]   = bR[0];
    *(float4*)&Bs[0][brow+8][bcol] = bR[1];
    __syncthreads();

    int nt = K/16;
    for (int tI = 0; tI < nt; tI++) {
        if (tI + 1 < nt) {
            int k0 = (tI + 1)*16;
            #pragma unroll
            for (int i = 0; i < 4; i++) aR[i] = *(const float4*)(aptr + k0 + i*4);
            #pragma unroll
            for (int i = 0; i < 2; i++)
                bR[i] = bval ? *(const float4*)(Buse + (size_t)(k0 + brow + i*8)*ldb + gCol)
                             : make_float4(0.f,0.f,0.f,0.f);
        }
        int buf = tI & 1;
        #pragma unroll
        for (int k = 0; k < 16; k++) {
            float a[8], bfr[8];
            *(float4*)&a[0]   = *(const float4*)&As[buf][k][ty*8];
            *(float4*)&a[4]   = *(const float4*)&As[buf][k][ty*8 + 4];
            *(float4*)&bfr[0] = *(const float4*)&Bs[buf][k][tx*8];
            *(float4*)&bfr[4] = *(const float4*)&Bs[buf][k][tx*8 + 4];
            #pragma unroll
            for (int i = 0; i < 8; i++)
                #pragma unroll
                for (int jx = 0; jx < 8; jx++)
                    acc[i][jx] = fmaf(a[i], bfr[jx], acc[i][jx]);
        }
        __syncthreads();
        if (tI + 1 < nt) {
            int nb = buf ^ 1;
            #pragma unroll
            for (int i = 0; i < 4; i++) {
                As[nb][i*4+0][arow] = aR[i].x; As[nb][i*4+1][arow] = aR[i].y;
                As[nb][i*4+2][arow] = aR[i].z; As[nb][i*4+3][arow] = aR[i].w;
            }
            *(float4*)&Bs[nb][brow][bcol]   = bR[0];
            *(float4*)&Bs[nb][brow+8][bcol] = bR[1];
        }
        __syncthreads();
    }

    #pragma unroll
    for (int i = 0; i < 8; i++) {
        int r = rowBase + ty*8 + i;
        int act = ract ? ract[r] : 1;
        float* crow = Cuse + (size_t)r*ldc;
        #pragma unroll
        for (int jx = 0; jx < 8; jx++) {
            int c = colBase + tx*8 + jx;
            if (c < N)
                crow[c] = act ? (acc[i][jx] + (bias ? bias[c] : 0.f)) : 0.f;
        }
    }
}

// ============================================================
extern "C" void kernel_launch(void* const* d_in, const int* in_sizes, int n_in,
                              void* d_out, int out_size) {
    const float* feat     = (const float*)d_in[0];
    const int*   captions = (const int*)  d_in[1];
    const int*   caplen   = (const int*)  d_in[2];
    const float* emb      = (const float*)d_in[3];
    const float* Wea = (const float*)d_in[4];  const float* bea = (const float*)d_in[5];
    const float* Wda = (const float*)d_in[6];  const float* bda = (const float*)d_in[7];
    const float* Wfa = (const float*)d_in[8];  const float* bfa = (const float*)d_in[9];
    const float* Wih = (const float*)d_in[10]; const float* bih = (const float*)d_in[11];
    const float* Whh = (const float*)d_in[12]; const float* bhh = (const float*)d_in[13];
    const float* Wh0 = (const float*)d_in[14]; const float* bh0 = (const float*)d_in[15];
    const float* Wc0 = (const float*)d_in[16]; const float* bc0 = (const float*)d_in[17];
    const float* Wfb = (const float*)d_in[18]; const float* bfb = (const float*)d_in[19];
    const float* Wout = (const float*)d_in[20]; const float* bout = (const float*)d_in[21];

    float* out = (float*)d_out;
    float* out_pred  = out + OFF_PRED;
    float* out_alpha = out + OFF_ALPHA;
    float* out_caps  = out + OFF_CAPS;
    float* out_len   = out + OFF_LEN;
    float* out_sort  = out + OFF_SORT;

    // device pointer to g_hbuf for k_s1's hcur argument
    float* hbuf_dev = nullptr;
    cudaGetSymbolAddress((void**)&hbuf_dev, g_hbuf);

    // ---- prologue ----
    k_setup<<<1, 256>>>(captions, caplen, out_caps, out_len, out_sort);
    k_embgather<<<dim3(TDEC, BSZ), 128>>>(emb);
    k_transWihE<<<dim3(G4/32, EE/32), 256>>>(Wih);
    k_mean<<<dim3(DE/256, BSZ), 256>>>(feat);
    k_h0c0<<<128, 256>>>(Wh0, bh0, Wc0, bc0);
    // att1 = enc @ Wea + bea : M=6272, N=512, K=2048
    k_gemm_db<<<dim3(AA/64, (BSZ*PP)/128), 128>>>(feat, DE, Wea, AA, bea,
                                                  nullptr, 0, BSZ*PP, AA, DE, 1);
    // pre = embX @ WihET : M=640, N=2048, K=512
    k_gemm_db<<<dim3(G4/64, (TDEC*BSZ)/128), 128>>>(nullptr, 0, nullptr, 0, nullptr,
                                                    nullptr, 0, TDEC*BSZ, G4, EE, 0);

    // ---- recurrence ----
    for (int t = 0; t < TDEC; t++) {
        int cur = t & 1;
        const float* hcur = hbuf_dev + cur*BSZ*HH;
        k_s1<<<XX/8, 256>>>(hcur, Wda, bda, Wfb, bfb);
        k_s2a<<<dim3((PP + 7)/8, BSZ), 256>>>(Wfa, bfa);
        k_s2b<<<BSZ, 256>>>(t, out_alpha);
        k_s3<<<dim3(DE/256, BSZ), 256>>>(feat);
        k_s4f<<<HH/4, 256>>>(t, cur, Wih, bih, Whh, bhh);
    }

    // ---- epilogue: preds = Hall @ Wout + bout : M=640, N=30000, K=512 ----
    k_gemm_db<<<dim3((VV + 63)/64, (TDEC*BSZ)/128), 128>>>(nullptr, 0, Wout, VV, bout,
                                                           out_pred, VV, TDEC*BSZ, VV, HH, 2);
}

// round 4
// speedup vs baseline: 1.8949x; 1.1701x over previous
#include <cuda_runtime.h>
#include <math.h>

// ---- problem constants ----
#define BSZ   32
#define TT    22
#define PP    196
#define DE    2048
#define EE    512
#define HH    512
#define AA    512
#define VV    30000
#define TDEC  20
#define XX    2560   // E + DE
#define G4    2048   // 4*H
#define KAW   2048   // awe part of K in LSTM gemm
#define KS4   2560   // awe + h

// ---- output layout ----
#define OFF_PRED  0
#define OFF_ALPHA (BSZ*TDEC*VV)
#define OFF_CAPS  (OFF_ALPHA + BSZ*TDEC*PP)
#define OFF_LEN   (OFF_CAPS + BSZ*TT)
#define OFF_SORT  (OFF_LEN + BSZ)

// ---- device scratch ----
__device__ float g_att1[BSZ*PP*AA];        // 12.8 MB
__device__ float g_hbuf[2*BSZ*HH];
__device__ float g_c[BSZ*HH];
__device__ float g_att2[BSZ*AA];
__device__ float g_gateraw[BSZ*DE];
__device__ float g_escore[BSZ*PP];
__device__ float g_xawe[BSZ*KAW];
__device__ float g_Hall[TDEC*BSZ*HH];
__device__ float g_meanpart[4*BSZ*DE];
__device__ float g_embX[TDEC*BSZ*EE];
__device__ float g_WihET[EE*G4];           // transposed emb-part of Wih
__device__ float g_pre[TDEC*BSZ*G4];       // precomputed emb contribution
__device__ float g_WdaT[AA*HH];            // WdaT[col][k]
__device__ float g_WfbT[DE*HH];            // WfbT[col][k]
__device__ float g_Wh0T[HH*DE];            // Wh0T[col][k]
__device__ float g_Wc0T[HH*DE];
__device__ int   g_sortind[BSZ];
__device__ int   g_declen[BSZ];
__device__ int   g_caps[BSZ*TT];
__device__ int   g_rowmapA[BSZ*PP];
__device__ int   g_rowmapC[BSZ*TDEC];
__device__ int   g_activeC[BSZ*TDEC];

__device__ __forceinline__ float sigm(float x) { return 1.0f / (1.0f + expf(-x)); }

// packed f32x2 helpers (sm_100+)
#define PACKDUP(d, f) asm("mov.b64 %0, {%1, %1};" : "=l"(d) : "r"(__float_as_uint(f)))
#define FMA2(c, a, b) asm("fma.rn.f32x2 %0, %1, %2, %0;" : "+l"(c) : "l"(a), "l"(b))
#define UNPACK2(lo, hi, v) asm("mov.b64 {%0, %1}, %2;" : "=r"(lo), "=r"(hi) : "l"(v))

// ============================================================
// Setup
// ============================================================
__global__ void k_setup(const int* __restrict__ captions,
                        const int* __restrict__ cap_len,
                        float* __restrict__ out_caps,
                        float* __restrict__ out_len,
                        float* __restrict__ out_sort) {
    int tid = threadIdx.x;
    __shared__ int s_len[BSZ];
    __shared__ int s_sort[BSZ];
    __shared__ int s_dec[BSZ];
    if (tid < BSZ) s_len[tid] = cap_len[tid];
    __syncthreads();
    if (tid < BSZ) {
        int li = s_len[tid];
        int rank = 0;
        for (int j = 0; j < BSZ; j++) {
            int lj = s_len[j];
            if (lj > li || (lj == li && j < tid)) rank++;
        }
        s_sort[rank] = tid;
    }
    __syncthreads();
    if (tid < BSZ) {
        int src = s_sort[tid];
        g_sortind[tid] = src;
        int L = s_len[src];
        g_declen[tid] = L - 1;
        s_dec[tid]    = L - 1;
        out_len[tid]  = (float)L;
        out_sort[tid] = (float)src;
    }
    __syncthreads();
    for (int i = tid; i < BSZ*TT; i += blockDim.x) {
        int b = i / TT, t = i % TT;
        int v = captions[t*BSZ + s_sort[b]];
        g_caps[i] = v;
        out_caps[i] = (float)v;
    }
    for (int i = tid; i < BSZ*PP; i += blockDim.x) {
        int b = i / PP, p = i % PP;
        g_rowmapA[i] = s_sort[b]*PP + p;
    }
    for (int i = tid; i < BSZ*TDEC; i += blockDim.x) {
        int b = i / TDEC, t = i % TDEC;
        g_rowmapC[i] = t*BSZ + b;
        g_activeC[i] = (t < s_dec[b]) ? 1 : 0;
    }
}

// ============================================================
// Gather embeddings
// ============================================================
__global__ void k_embgather(const float* __restrict__ emb) {
    int t = blockIdx.x, b = blockIdx.y;
    int tok = g_caps[b*TT + t];
    const float* src = emb + (size_t)tok*EE;
    float* dst = g_embX + ((size_t)t*BSZ + b)*EE;
    for (int e = threadIdx.x; e < EE; e += blockDim.x) dst[e] = src[e];
}

// ============================================================
// Generic 32x32-tiled transpose: dst[c*dstLd + r] = src[r*srcLd + c]
// ============================================================
__global__ void __launch_bounds__(256) k_trans(const float* __restrict__ src, int srcLd,
                                               float* __restrict__ dst, int dstLd) {
    __shared__ float ts[32][33];
    int r0 = blockIdx.x*32, c0 = blockIdx.y*32;
    int tx = threadIdx.x & 31, ty = threadIdx.x >> 5;
    #pragma unroll
    for (int rr = ty; rr < 32; rr += 8)
        ts[rr][tx] = src[(size_t)(r0 + rr)*srcLd + c0 + tx];
    __syncthreads();
    #pragma unroll
    for (int rr = ty; rr < 32; rr += 8)
        dst[(size_t)(c0 + rr)*dstLd + r0 + tx] = ts[tx][rr];
}

// ============================================================
// mean partials: 4-way split over p
// ============================================================
__global__ void k_meanpart(const float* __restrict__ feat) {
    int b = blockIdx.y, ps = blockIdx.z;
    int d = blockIdx.x*256 + threadIdx.x;
    const float* base = feat + (size_t)g_sortind[b]*PP*DE + d;
    float s = 0.f;
    int p0 = ps*49;
    #pragma unroll 7
    for (int p = p0; p < p0 + 49; p++) s += base[(size_t)p*DE];
    g_meanpart[((ps*BSZ) + b)*DE + d] = s;
}

// ============================================================
// h0/c0 with transposed weights (coalesced)
// ============================================================
__global__ void __launch_bounds__(256) k_h0c0(const float* __restrict__ bh0,
                                              const float* __restrict__ bc0) {
    __shared__ float xs[BSZ][128];
    int tid = threadIdx.x, lane = tid & 31, w = tid >> 5;
    int c0 = blockIdx.x*8 + (w & 1)*4;
    int b0 = (w >> 1)*8;
    float acc[4][8];
    #pragma unroll
    for (int i = 0; i < 4; i++)
        #pragma unroll
        for (int jx = 0; jx < 8; jx++) acc[i][jx] = 0.f;

    for (int kt = 0; kt < DE/128; kt++) {
        #pragma unroll
        for (int s = 0; s < 16; s++) {
            int idx = tid + s*256;
            int bb = idx >> 7, kk = idx & 127;
            int gd = kt*128 + kk;
            float m = g_meanpart[(0*BSZ + bb)*DE + gd] + g_meanpart[(1*BSZ + bb)*DE + gd]
                    + g_meanpart[(2*BSZ + bb)*DE + gd] + g_meanpart[(3*BSZ + bb)*DE + gd];
            xs[bb][kk] = m * (1.0f/PP);
        }
        __syncthreads();
        #pragma unroll
        for (int kk4 = 0; kk4 < 4; kk4++) {
            int k = kt*128 + kk4*32 + lane;
            float wv[4];
            #pragma unroll
            for (int cc = 0; cc < 4; cc++) {
                int col = c0 + cc;
                wv[cc] = (col < HH) ? g_Wh0T[(size_t)col*DE + k] : g_Wc0T[(size_t)(col - HH)*DE + k];
            }
            #pragma unroll
            for (int cc = 0; cc < 4; cc++)
                #pragma unroll
                for (int bb = 0; bb < 8; bb++)
                    acc[cc][bb] = fmaf(wv[cc], xs[b0+bb][kk4*32+lane], acc[cc][bb]);
        }
        __syncthreads();
    }
    float out = 0.f;
    #pragma unroll
    for (int cc = 0; cc < 4; cc++)
        #pragma unroll
        for (int bb = 0; bb < 8; bb++) {
            float v = acc[cc][bb];
            #pragma unroll
            for (int off = 16; off; off >>= 1) v += __shfl_xor_sync(0xffffffffu, v, off);
            if (lane == cc*8 + bb) out = v;
        }
    int cc = lane >> 3, bb = lane & 7;
    int col = c0 + cc, b = b0 + bb;
    if (col < HH) g_hbuf[b*HH + col]   = out + bh0[col];
    else          g_c[b*HH + col - HH] = out + bc0[col - HH];
}

// ============================================================
// S1: att2 = h@Wda + bda ; gate_raw = h@Wfb + bfb (transposed W)
// ============================================================
__global__ void __launch_bounds__(256) k_s1(const float* __restrict__ hcur,
                                            const float* __restrict__ bda,
                                            const float* __restrict__ bfb) {
    __shared__ float xs[BSZ][128];
    int tid = threadIdx.x, lane = tid & 31, w = tid >> 5;
    int c0 = blockIdx.x*8 + (w & 1)*4;
    int b0 = (w >> 1)*8;
    float acc[4][8];
    #pragma unroll
    for (int i = 0; i < 4; i++)
        #pragma unroll
        for (int jx = 0; jx < 8; jx++) acc[i][jx] = 0.f;

    #pragma unroll
    for (int kt = 0; kt < HH/128; kt++) {
        #pragma unroll
        for (int s = 0; s < 16; s++) {
            int idx = tid + s*256;
            int bb = idx >> 7, kk = idx & 127;
            xs[bb][kk] = hcur[bb*HH + kt*128 + kk];
        }
        __syncthreads();
        #pragma unroll
        for (int kk4 = 0; kk4 < 4; kk4++) {
            int k = kt*128 + kk4*32 + lane;
            float wv[4];
            #pragma unroll
            for (int cc = 0; cc < 4; cc++) {
                int col = c0 + cc;
                wv[cc] = (col < AA) ? g_WdaT[(size_t)col*HH + k] : g_WfbT[(size_t)(col - AA)*HH + k];
            }
            #pragma unroll
            for (int cc = 0; cc < 4; cc++)
                #pragma unroll
                for (int bb = 0; bb < 8; bb++)
                    acc[cc][bb] = fmaf(wv[cc], xs[b0+bb][kk4*32+lane], acc[cc][bb]);
        }
        __syncthreads();
    }
    float out = 0.f;
    #pragma unroll
    for (int cc = 0; cc < 4; cc++)
        #pragma unroll
        for (int bb = 0; bb < 8; bb++) {
            float v = acc[cc][bb];
            #pragma unroll
            for (int off = 16; off; off >>= 1) v += __shfl_xor_sync(0xffffffffu, v, off);
            if (lane == cc*8 + bb) out = v;
        }
    int cc = lane >> 3, bb = lane & 7;
    int col = c0 + cc, b = b0 + bb;
    if (col < AA) g_att2[b*AA + col]         = out + bda[col];
    else          g_gateraw[b*DE + col - AA] = out + bfb[col - AA];
}

// ============================================================
// S2a: scores with float4 loads. grid (25, 32) x 256
// ============================================================
__global__ void __launch_bounds__(256) k_s2a(const float* __restrict__ Wfa, const float* __restrict__ bfa) {
    int b = blockIdx.y;
    int tid = threadIdx.x, lane = tid & 31, w = tid >> 5;
    __shared__ float4 att2s4[AA/4], wfas4[AA/4];
    if (tid < AA/4) {
        att2s4[tid] = ((const float4*)(g_att2 + b*AA))[tid];
        wfas4[tid]  = ((const float4*)Wfa)[tid];
    }
    __syncthreads();
    int p = blockIdx.x*8 + w;
    if (p >= PP) return;
    const float4* row4 = (const float4*)(g_att1 + ((size_t)b*PP + p)*AA);
    float acc = 0.f;
    #pragma unroll
    for (int c = 0; c < 4; c++) {
        int idx = c*32 + lane;
        float4 v = row4[idx];
        float4 a2 = att2s4[idx];
        float4 wf = wfas4[idx];
        acc = fmaf(fmaxf(v.x + a2.x, 0.f), wf.x, acc);
        acc = fmaf(fmaxf(v.y + a2.y, 0.f), wf.y, acc);
        acc = fmaf(fmaxf(v.z + a2.z, 0.f), wf.z, acc);
        acc = fmaf(fmaxf(v.w + a2.w, 0.f), wf.w, acc);
    }
    #pragma unroll
    for (int off = 16; off; off >>= 1) acc += __shfl_xor_sync(0xffffffffu, acc, off);
    if (lane == 0) g_escore[b*PP + p] = acc + bfa[0];
}

// ============================================================
// S3f: per-block redundant softmax + awe + gate. grid (8, 32).
// block 0 of each b also writes masked alphas output.
// ============================================================
__global__ void __launch_bounds__(256) k_s3f(int t, const float* __restrict__ feat,
                                             float* __restrict__ out_alphas) {
    int b = blockIdx.y, tid = threadIdx.x;
    __shared__ float als[PP];
    __shared__ float sred[256];
    float e = (tid < PP) ? g_escore[b*PP + tid] : -3.0e38f;
    sred[tid] = e;
    __syncthreads();
    for (int s = 128; s > 0; s >>= 1) { if (tid < s) sred[tid] = fmaxf(sred[tid], sred[tid+s]); __syncthreads(); }
    float mx = sred[0];
    __syncthreads();
    float ex = (tid < PP) ? expf(e - mx) : 0.f;
    sred[tid] = ex;
    __syncthreads();
    for (int s = 128; s > 0; s >>= 1) { if (tid < s) sred[tid] += sred[tid+s]; __syncthreads(); }
    float inv = 1.0f / sred[0];
    if (tid < PP) {
        float al = ex * inv;
        als[tid] = al;
        if (blockIdx.x == 0) {
            int active = (t < g_declen[b]);
            out_alphas[((size_t)b*TDEC + t)*PP + tid] = active ? al : 0.f;
        }
    }
    __syncthreads();

    int d = blockIdx.x*256 + tid;
    const float* base = feat + (size_t)g_sortind[b]*PP*DE + d;
    float s = 0.f;
    #pragma unroll 7
    for (int p = 0; p < PP; p++) s = fmaf(als[p], base[(size_t)p*DE], s);
    float gr = g_gateraw[b*DE + d];
    g_xawe[b*KAW + d] = sigm(gr) * s;
}

// ============================================================
// S4 fused: gates GEMM (K=2560) + LSTM cell (unchanged)
// ============================================================
__global__ void __launch_bounds__(256) k_s4f(int t, int cur,
        const float* __restrict__ Wih, const float* __restrict__ bih,
        const float* __restrict__ Whh, const float* __restrict__ bhh) {
    __shared__ float xs[BSZ][128];
    __shared__ float red[4][BSZ][33];
    __shared__ float gsum[16][BSZ];
    int tid = threadIdx.x, lane = tid & 31, w = tid >> 5;
    int jBlock = blockIdx.x*4;
    int r0 = (w >> 1)*4;
    int bh = (w & 1)*16;
    const float* hcur = g_hbuf + cur*BSZ*HH;
    float*       hnxt = g_hbuf + (1 - cur)*BSZ*HH;

    float acc[4][16];
    #pragma unroll
    for (int i = 0; i < 4; i++)
        #pragma unroll
        for (int jx = 0; jx < 16; jx++) acc[i][jx] = 0.f;

    const float* wrowIH[4];
    const float* wrowHH[4];
    #pragma unroll
    for (int cc = 0; cc < 4; cc++) {
        int v = r0 + cc;
        int wr = (v >> 2)*HH + jBlock + (v & 3);
        wrowIH[cc] = Wih + (size_t)wr*XX + EE;
        wrowHH[cc] = Whh + (size_t)wr*HH;
    }

    float pv[16];
    #pragma unroll
    for (int s = 0; s < 16; s++) {
        int idx = tid + s*256;
        int bb = idx >> 7, kk = idx & 127;
        pv[s] = g_xawe[bb*KAW + kk];
    }
    #pragma unroll
    for (int s = 0; s < 16; s++) {
        int idx = tid + s*256;
        xs[idx >> 7][idx & 127] = pv[s];
    }
    __syncthreads();

    for (int kt = 0; kt < KS4/128; kt++) {
        if (kt + 1 < KS4/128) {
            int gk0 = (kt + 1)*128;
            #pragma unroll
            for (int s = 0; s < 16; s++) {
                int idx = tid + s*256;
                int bb = idx >> 7, kk = idx & 127;
                int gk = gk0 + kk;
                pv[s] = (gk < KAW) ? g_xawe[bb*KAW + gk] : hcur[bb*HH + gk - KAW];
            }
        }
        #pragma unroll
        for (int kk4 = 0; kk4 < 4; kk4++) {
            int gk = kt*128 + kk4*32 + lane;
            float wv[4];
            #pragma unroll
            for (int cc = 0; cc < 4; cc++)
                wv[cc] = (gk < KAW) ? wrowIH[cc][gk] : wrowHH[cc][gk - KAW];
            #pragma unroll
            for (int bb = 0; bb < 16; bb++) {
                float xv = xs[bh + bb][kk4*32 + lane];
                #pragma unroll
                for (int cc = 0; cc < 4; cc++)
                    acc[cc][bb] = fmaf(wv[cc], xv, acc[cc][bb]);
            }
        }
        __syncthreads();
        if (kt + 1 < KS4/128) {
            #pragma unroll
            for (int s = 0; s < 16; s++) {
                int idx = tid + s*256;
                xs[idx >> 7][idx & 127] = pv[s];
            }
        }
        __syncthreads();
    }

    for (int rnd = 0; rnd < 4; rnd++) {
        if ((w >> 1) == rnd) {
            #pragma unroll
            for (int cc = 0; cc < 4; cc++)
                #pragma unroll
                for (int bb = 0; bb < 16; bb++)
                    red[cc][bh + bb][lane] = acc[cc][bb];
        }
        __syncthreads();
        if (tid < 128) {
            int cc = tid >> 5, b = tid & 31;
            float s = 0.f;
            #pragma unroll
            for (int l = 0; l < 32; l++) s += red[cc][b][l];
            gsum[rnd*4 + cc][b] = s;
        }
        __syncthreads();
    }

    if (tid < 128) {
        int jj = tid >> 5, b = tid & 31;
        int j = jBlock + jj;
        size_t pb = ((size_t)t*BSZ + b)*G4;
        float gi = gsum[0  + jj][b] + bih[0*HH + j] + bhh[0*HH + j] + g_pre[pb + 0*HH + j];
        float gf = gsum[4  + jj][b] + bih[1*HH + j] + bhh[1*HH + j] + g_pre[pb + 1*HH + j];
        float gg = gsum[8  + jj][b] + bih[2*HH + j] + bhh[2*HH + j] + g_pre[pb + 2*HH + j];
        float go = gsum[12 + jj][b] + bih[3*HH + j] + bhh[3*HH + j] + g_pre[pb + 3*HH + j];
        float c  = g_c[b*HH + j];
        float cn = sigm(gf)*c + sigm(gi)*tanhf(gg);
        float hn = sigm(go)*tanhf(cn);
        int active = (t < g_declen[b]);
        if (active) g_c[b*HH + j] = cn;
        hnxt[b*HH + j] = active ? hn : hcur[b*HH + j];
        g_Hall[((size_t)t*BSZ + b)*HH + j] = hn;
    }
}

// ============================================================
// Double-buffered SGEMM with packed f32x2 FMAs.
// 128x64 tile, K-tile 16, 128 threads, 8x8 microtile.
// ============================================================
__global__ void __launch_bounds__(128) k_gemm_db(const float* __restrict__ Aext, int lda_,
                                                 const float* __restrict__ Bext, int ldb_,
                                                 const float* __restrict__ biasext,
                                                 float* __restrict__ Cext, int ldc_,
                                                 int M, int N, int K, int mode) {
    __shared__ __align__(16) float As[2][16][128];
    __shared__ __align__(16) float Bs[2][16][64];
    int tid = threadIdx.x;
    int rowBase = blockIdx.y*128, colBase = blockIdx.x*64;

    const float* Ause; const float* Buse; const float* bias; float* Cuse;
    int lda, ldb, ldc;
    const int* rowmap = nullptr; const int* ract = nullptr;
    if (mode == 0) { Ause = g_embX; lda = EE;  Buse = g_WihET; ldb = G4; bias = nullptr; Cuse = g_pre;  ldc = G4; }
    else if (mode == 1) { Ause = Aext; lda = lda_; Buse = Bext; ldb = ldb_; bias = biasext; Cuse = g_att1; ldc = AA; rowmap = g_rowmapA; }
    else { Ause = g_Hall; lda = HH; Buse = Bext; ldb = ldb_; bias = biasext; Cuse = Cext; ldc = ldc_; rowmap = g_rowmapC; ract = g_activeC; }

    int arow = tid;
    int gRow = rowBase + arow;
    int amap = rowmap ? rowmap[gRow] : gRow;
    const float* aptr = Ause + (size_t)amap*lda;

    int brow = tid >> 4;
    int bcol = (tid & 15)*4;
    int gCol = colBase + bcol;
    bool bval = (gCol < N);

    int tx = tid & 7, ty = tid >> 3;

    unsigned long long accp[4][8];
    #pragma unroll
    for (int q = 0; q < 4; q++)
        #pragma unroll
        for (int jx = 0; jx < 8; jx++) accp[q][jx] = 0ull;

    float4 aR[4], bR[2];
    #pragma unroll
    for (int i = 0; i < 4; i++) aR[i] = *(const float4*)(aptr + i*4);
    #pragma unroll
    for (int i = 0; i < 2; i++)
        bR[i] = bval ? *(const float4*)(Buse + (size_t)(brow + i*8)*ldb + gCol)
                     : make_float4(0.f,0.f,0.f,0.f);
    #pragma unroll
    for (int i = 0; i < 4; i++) {
        As[0][i*4+0][arow] = aR[i].x; As[0][i*4+1][arow] = aR[i].y;
        As[0][i*4+2][arow] = aR[i].z; As[0][i*4+3][arow] = aR[i].w;
    }
    *(float4*)&Bs[0][brow][bcol]   = bR[0];
    *(float4*)&Bs[0][brow+8][bcol] = bR[1];
    __syncthreads();

    int nt = K/16;
    for (int tI = 0; tI < nt; tI++) {
        if (tI + 1 < nt) {
            int k0 = (tI + 1)*16;
            #pragma unroll
            for (int i = 0; i < 4; i++) aR[i] = *(const float4*)(aptr + k0 + i*4);
            #pragma unroll
            for (int i = 0; i < 2; i++)
                bR[i] = bval ? *(const float4*)(Buse + (size_t)(k0 + brow + i*8)*ldb + gCol)
                             : make_float4(0.f,0.f,0.f,0.f);
        }
        int buf = tI & 1;
        #pragma unroll
        for (int k = 0; k < 16; k++) {
            unsigned long long ap[4];
            const unsigned long long* a64 = (const unsigned long long*)&As[buf][k][ty*8];
            ap[0] = a64[0]; ap[1] = a64[1]; ap[2] = a64[2]; ap[3] = a64[3];
            float bfr[8];
            *(float4*)&bfr[0] = *(const float4*)&Bs[buf][k][tx*8];
            *(float4*)&bfr[4] = *(const float4*)&Bs[buf][k][tx*8 + 4];
            unsigned long long b2[8];
            #pragma unroll
            for (int jx = 0; jx < 8; jx++) PACKDUP(b2[jx], bfr[jx]);
            #pragma unroll
            for (int q = 0; q < 4; q++)
                #pragma unroll
                for (int jx = 0; jx < 8; jx++)
                    FMA2(accp[q][jx], ap[q], b2[jx]);
        }
        __syncthreads();
        if (tI + 1 < nt) {
            int nb = buf ^ 1;
            #pragma unroll
            for (int i = 0; i < 4; i++) {
                As[nb][i*4+0][arow] = aR[i].x; As[nb][i*4+1][arow] = aR[i].y;
                As[nb][i*4+2][arow] = aR[i].z; As[nb][i*4+3][arow] = aR[i].w;
            }
            *(float4*)&Bs[nb][brow][bcol]   = bR[0];
            *(float4*)&Bs[nb][brow+8][bcol] = bR[1];
        }
        __syncthreads();
    }

    #pragma unroll
    for (int q = 0; q < 4; q++) {
        int rA = rowBase + ty*8 + 2*q;
        int rB = rA + 1;
        int actA = ract ? ract[rA] : 1;
        int actB = ract ? ract[rB] : 1;
        float* crowA = Cuse + (size_t)rA*ldc;
        float* crowB = Cuse + (size_t)rB*ldc;
        #pragma unroll
        for (int jx = 0; jx < 8; jx++) {
            int c = colBase + tx*8 + jx;
            if (c < N) {
                unsigned lo, hi;
                UNPACK2(lo, hi, accp[q][jx]);
                float bsv = bias ? bias[c] : 0.f;
                crowA[c] = actA ? (__uint_as_float(lo) + bsv) : 0.f;
                crowB[c] = actB ? (__uint_as_float(hi) + bsv) : 0.f;
            }
        }
    }
}

// ============================================================
extern "C" void kernel_launch(void* const* d_in, const int* in_sizes, int n_in,
                              void* d_out, int out_size) {
    const float* feat     = (const float*)d_in[0];
    const int*   captions = (const int*)  d_in[1];
    const int*   caplen   = (const int*)  d_in[2];
    const float* emb      = (const float*)d_in[3];
    const float* Wea = (const float*)d_in[4];  const float* bea = (const float*)d_in[5];
    const float* Wda = (const float*)d_in[6];  const float* bda = (const float*)d_in[7];
    const float* Wfa = (const float*)d_in[8];  const float* bfa = (const float*)d_in[9];
    const float* Wih = (const float*)d_in[10]; const float* bih = (const float*)d_in[11];
    const float* Whh = (const float*)d_in[12]; const float* bhh = (const float*)d_in[13];
    const float* Wh0 = (const float*)d_in[14]; const float* bh0 = (const float*)d_in[15];
    const float* Wc0 = (const float*)d_in[16]; const float* bc0 = (const float*)d_in[17];
    const float* Wfb = (const float*)d_in[18]; const float* bfb = (const float*)d_in[19];
    const float* Wout = (const float*)d_in[20]; const float* bout = (const float*)d_in[21];

    float* out = (float*)d_out;
    float* out_pred  = out + OFF_PRED;
    float* out_alpha = out + OFF_ALPHA;
    float* out_caps  = out + OFF_CAPS;
    float* out_len   = out + OFF_LEN;
    float* out_sort  = out + OFF_SORT;

    float* hbuf_dev = nullptr;
    cudaGetSymbolAddress((void**)&hbuf_dev, g_hbuf);
    float* WihET_dev = nullptr; cudaGetSymbolAddress((void**)&WihET_dev, g_WihET);
    float* WdaT_dev = nullptr;  cudaGetSymbolAddress((void**)&WdaT_dev, g_WdaT);
    float* WfbT_dev = nullptr;  cudaGetSymbolAddress((void**)&WfbT_dev, g_WfbT);
    float* Wh0T_dev = nullptr;  cudaGetSymbolAddress((void**)&Wh0T_dev, g_Wh0T);
    float* Wc0T_dev = nullptr;  cudaGetSymbolAddress((void**)&Wc0T_dev, g_Wc0T);

    // ---- prologue ----
    k_setup<<<1, 256>>>(captions, caplen, out_caps, out_len, out_sort);
    k_embgather<<<dim3(TDEC, BSZ), 128>>>(emb);
    // transposes: dst[c*dstLd + r] = src[r*srcLd + c], grid (R/32, C/32)
    k_trans<<<dim3(2048/32, 512/32), 256>>>(Wih, XX, WihET_dev, G4);   // WihE part
    k_trans<<<dim3(512/32, 512/32),  256>>>(Wda, AA, WdaT_dev, HH);
    k_trans<<<dim3(512/32, 2048/32), 256>>>(Wfb, DE, WfbT_dev, HH);
    k_trans<<<dim3(2048/32, 512/32), 256>>>(Wh0, HH, Wh0T_dev, DE);
    k_trans<<<dim3(2048/32, 512/32), 256>>>(Wc0, HH, Wc0T_dev, DE);
    k_meanpart<<<dim3(DE/256, BSZ, 4), 256>>>(feat);
    k_h0c0<<<128, 256>>>(bh0, bc0);
    // att1 = enc @ Wea + bea : M=6272, N=512, K=2048
    k_gemm_db<<<dim3(AA/64, (BSZ*PP)/128), 128>>>(feat, DE, Wea, AA, bea,
                                                  nullptr, 0, BSZ*PP, AA, DE, 1);
    // pre = embX @ WihET : M=640, N=2048, K=512
    k_gemm_db<<<dim3(G4/64, (TDEC*BSZ)/128), 128>>>(nullptr, 0, nullptr, 0, nullptr,
                                                    nullptr, 0, TDEC*BSZ, G4, EE, 0);

    // ---- recurrence ----
    for (int t = 0; t < TDEC; t++) {
        int cur = t & 1;
        const float* hcur = hbuf_dev + cur*BSZ*HH;
        k_s1<<<XX/8, 256>>>(hcur, bda, bfb);
        k_s2a<<<dim3((PP + 7)/8, BSZ), 256>>>(Wfa, bfa);
        k_s3f<<<dim3(DE/256, BSZ), 256>>>(t, feat, out_alpha);
        k_s4f<<<HH/4, 256>>>(t, cur, Wih, bih, Whh, bhh);
    }

    // ---- epilogue: preds = Hall @ Wout + bout : M=640, N=30000, K=512 ----
    k_gemm_db<<<dim3((VV + 63)/64, (TDEC*BSZ)/128), 128>>>(nullptr, 0, Wout, VV, bout,
                                                           out_pred, VV, TDEC*BSZ, VV, HH, 2);
}